// round 2
// baseline (speedup 1.0000x reference)
#include <cuda_runtime.h>
#include <math.h>

#define BATCH 2
#define SEQ   4096
#define HID   768
#define NHEAD 12
#define HDIM  64
#define MROWS (BATCH * SEQ)   // 8192

// ---------------- scratch (device globals: allocation-free) ----------------
__device__ float g_Q[(size_t)MROWS * HID];
__device__ float g_K[(size_t)MROWS * HID];
__device__ float g_V[(size_t)MROWS * HID];
__device__ float g_C[(size_t)MROWS * HID];
__device__ float g_L[(size_t)BATCH * NHEAD * SEQ];

// ---------------------------------------------------------------------------
// GEMM: Y[M,768] = X[M,768] @ W[768,768]^T + bias
// BM=128, BN=64, BK=16, 256 threads, 8x4 micro-tile per thread.
// Both X and W are K-contiguous (NT gemm) -> float4 global loads.
// ---------------------------------------------------------------------------
__global__ __launch_bounds__(256) void gemm_xwT(
    const float* __restrict__ X, const float* __restrict__ W,
    const float* __restrict__ bias, float* __restrict__ Y) {
    const int K = HID, N = HID;
    __shared__ float Xs[16][128];
    __shared__ float Ws[16][64];

    int tid = threadIdx.x;
    int tx = tid & 15, ty = tid >> 4;
    int row0 = blockIdx.y * 128;
    int col0 = blockIdx.x * 64;

    float acc[8][4];
#pragma unroll
    for (int i = 0; i < 8; i++)
#pragma unroll
        for (int j = 0; j < 4; j++) acc[i][j] = 0.f;

    int xr = tid >> 1, xk = (tid & 1) * 8;     // 128 rows x 16k, 2 float4/thread
    int wr = tid >> 2, wk = (tid & 3) * 4;     // 64 rows x 16k, 1 float4/thread
    const float* xp = X + (size_t)(row0 + xr) * K + xk;
    const float* wp = W + (size_t)(col0 + wr) * K + wk;

    for (int k0 = 0; k0 < K; k0 += 16) {
        float4 x0 = *(const float4*)(xp + k0);
        float4 x1 = *(const float4*)(xp + k0 + 4);
        float4 w0 = *(const float4*)(wp + k0);
        Xs[xk + 0][xr] = x0.x; Xs[xk + 1][xr] = x0.y;
        Xs[xk + 2][xr] = x0.z; Xs[xk + 3][xr] = x0.w;
        Xs[xk + 4][xr] = x1.x; Xs[xk + 5][xr] = x1.y;
        Xs[xk + 6][xr] = x1.z; Xs[xk + 7][xr] = x1.w;
        Ws[wk + 0][wr] = w0.x; Ws[wk + 1][wr] = w0.y;
        Ws[wk + 2][wr] = w0.z; Ws[wk + 3][wr] = w0.w;
        __syncthreads();
#pragma unroll
        for (int kk = 0; kk < 16; ++kk) {
            float4 a0 = *(const float4*)&Xs[kk][ty * 8];
            float4 a1 = *(const float4*)&Xs[kk][ty * 8 + 4];
            float4 b0 = *(const float4*)&Ws[kk][tx * 4];
            float av[8] = {a0.x, a0.y, a0.z, a0.w, a1.x, a1.y, a1.z, a1.w};
            float bv[4] = {b0.x, b0.y, b0.z, b0.w};
#pragma unroll
            for (int i = 0; i < 8; i++)
#pragma unroll
                for (int j = 0; j < 4; j++) acc[i][j] += av[i] * bv[j];
        }
        __syncthreads();
    }

    float4 bb = *(const float4*)&bias[col0 + tx * 4];
#pragma unroll
    for (int i = 0; i < 8; i++) {
        float4 o;
        o.x = acc[i][0] + bb.x; o.y = acc[i][1] + bb.y;
        o.z = acc[i][2] + bb.z; o.w = acc[i][3] + bb.w;
        *(float4*)&Y[(size_t)(row0 + ty * 8 + i) * N + col0 + tx * 4] = o;
    }
}

// ---------------------------------------------------------------------------
// Pass 1: per (b,h,q-tile of 64): scores = QK^T/8, mask, e = exp(s) written
// UNNORMALIZED to the attn output region; row sums -> g_L.
// 256 threads, 4x4 micro-tile over a 64x64 score tile.
// ---------------------------------------------------------------------------
__global__ __launch_bounds__(256) void attn_pass1(
    const float* __restrict__ Q, const float* __restrict__ Kc,
    const int* __restrict__ mask, float* __restrict__ attn,
    float* __restrict__ Lsum) {
    __shared__ float Qs[64][64];   // [d][r]
    __shared__ float Ks[64][64];   // [d][c]

    int bh = blockIdx.y;
    int b = bh / NHEAD, h = bh - b * NHEAD;
    int q0 = blockIdx.x * 64;
    int tid = threadIdx.x, tx = tid & 15, ty = tid >> 4;

    {   // load Q tile transposed: Qs[d][r]
        int r = tid >> 2, dp = (tid & 3) * 16;
        const float* qp = Q + (size_t)(b * SEQ + q0 + r) * HID + h * HDIM + dp;
#pragma unroll
        for (int i = 0; i < 16; i += 4) {
            float4 v = *(const float4*)(qp + i);
            Qs[dp + i + 0][r] = v.x; Qs[dp + i + 1][r] = v.y;
            Qs[dp + i + 2][r] = v.z; Qs[dp + i + 3][r] = v.w;
        }
    }

    float lsum[4] = {0.f, 0.f, 0.f, 0.f};
    float* abase = attn + ((size_t)bh * SEQ + q0) * SEQ;
    const int* mbase = mask + b * SEQ;

    for (int kt = 0; kt < SEQ / 64; ++kt) {
        __syncthreads();
        {   // load K tile transposed: Ks[d][c]
            int c = tid >> 2, dp = (tid & 3) * 16;
            const float* kp = Kc + (size_t)(b * SEQ + kt * 64 + c) * HID + h * HDIM + dp;
#pragma unroll
            for (int i = 0; i < 16; i += 4) {
                float4 v = *(const float4*)(kp + i);
                Ks[dp + i + 0][c] = v.x; Ks[dp + i + 1][c] = v.y;
                Ks[dp + i + 2][c] = v.z; Ks[dp + i + 3][c] = v.w;
            }
        }
        __syncthreads();

        float acc[4][4];
#pragma unroll
        for (int i = 0; i < 4; i++)
#pragma unroll
            for (int j = 0; j < 4; j++) acc[i][j] = 0.f;

#pragma unroll
        for (int d = 0; d < 64; ++d) {
            float4 a  = *(const float4*)&Qs[d][ty * 4];
            float4 bb = *(const float4*)&Ks[d][tx * 4];
            float av[4] = {a.x, a.y, a.z, a.w};
            float bv[4] = {bb.x, bb.y, bb.z, bb.w};
#pragma unroll
            for (int i = 0; i < 4; i++)
#pragma unroll
                for (int j = 0; j < 4; j++) acc[i][j] += av[i] * bv[j];
        }

        int c0 = kt * 64 + tx * 4;
        int m0 = mbase[c0 + 0], m1 = mbase[c0 + 1];
        int m2 = mbase[c0 + 2], m3 = mbase[c0 + 3];
#pragma unroll
        for (int i = 0; i < 4; ++i) {
            float4 e;
            e.x = m0 ? __expf(acc[i][0] * 0.125f) : 0.f;
            e.y = m1 ? __expf(acc[i][1] * 0.125f) : 0.f;
            e.z = m2 ? __expf(acc[i][2] * 0.125f) : 0.f;
            e.w = m3 ? __expf(acc[i][3] * 0.125f) : 0.f;
            *(float4*)&abase[(size_t)(ty * 4 + i) * SEQ + c0] = e;
            lsum[i] += e.x + e.y + e.z + e.w;
        }
    }

    // reduce row sums across the 16 tx lanes sharing each row
#pragma unroll
    for (int i = 0; i < 4; ++i) {
        float v = lsum[i];
        v += __shfl_xor_sync(0xffffffffu, v, 8);
        v += __shfl_xor_sync(0xffffffffu, v, 4);
        v += __shfl_xor_sync(0xffffffffu, v, 2);
        v += __shfl_xor_sync(0xffffffffu, v, 1);
        if (tx == 0) Lsum[(size_t)bh * SEQ + q0 + ty * 4 + i] = v;
    }
}

// ---------------------------------------------------------------------------
// Pass 2: read back e tiles, scale by 1/L -> write normalized attn_weights,
// and fuse context = P @ V on the in-smem tile. Context -> g_C.
// ---------------------------------------------------------------------------
__global__ __launch_bounds__(256) void attn_pass2(
    const float* __restrict__ V, const float* __restrict__ Lsum,
    float* __restrict__ attn, float* __restrict__ Ctx) {
    __shared__ float Ps[64][64];   // [r][c]
    __shared__ float Vs[64][64];   // [c][d]

    int bh = blockIdx.y;
    int b = bh / NHEAD, h = bh - b * NHEAD;
    int q0 = blockIdx.x * 64;
    int tid = threadIdx.x, tx = tid & 15, ty = tid >> 4;

    float linv[4];
#pragma unroll
    for (int i = 0; i < 4; ++i)
        linv[i] = 1.0f / Lsum[(size_t)bh * SEQ + q0 + ty * 4 + i];

    float acc[4][4];
#pragma unroll
    for (int i = 0; i < 4; i++)
#pragma unroll
        for (int j = 0; j < 4; j++) acc[i][j] = 0.f;

    float* abase = attn + ((size_t)bh * SEQ + q0) * SEQ;

    for (int kt = 0; kt < SEQ / 64; ++kt) {
        __syncthreads();
        {   // V tile: Vs[c][d], natural orientation, float4 direct
            int c = tid >> 2, dp = (tid & 3) * 16;
            const float* vp = V + (size_t)(b * SEQ + kt * 64 + c) * HID + h * HDIM + dp;
#pragma unroll
            for (int i = 0; i < 16; i += 4)
                *(float4*)&Vs[c][dp + i] = *(const float4*)(vp + i);
        }
        // normalize e tile, write back to gmem, stage in smem
#pragma unroll
        for (int i = 0; i < 4; ++i) {
            float* ap = &abase[(size_t)(ty * 4 + i) * SEQ + kt * 64 + tx * 4];
            float4 e = *(const float4*)ap;
            e.x *= linv[i]; e.y *= linv[i]; e.z *= linv[i]; e.w *= linv[i];
            *(float4*)ap = e;
            *(float4*)&Ps[ty * 4 + i][tx * 4] = e;
        }
        __syncthreads();

#pragma unroll
        for (int c = 0; c < 64; c += 4) {
            float pa[4][4];
            float vv[4][4];
#pragma unroll
            for (int i = 0; i < 4; ++i) {
                float4 p = *(const float4*)&Ps[ty * 4 + i][c];
                pa[i][0] = p.x; pa[i][1] = p.y; pa[i][2] = p.z; pa[i][3] = p.w;
            }
#pragma unroll
            for (int cc = 0; cc < 4; ++cc) {
                float4 v = *(const float4*)&Vs[c + cc][tx * 4];
                vv[cc][0] = v.x; vv[cc][1] = v.y; vv[cc][2] = v.z; vv[cc][3] = v.w;
            }
#pragma unroll
            for (int i = 0; i < 4; ++i)
#pragma unroll
                for (int cc = 0; cc < 4; ++cc)
#pragma unroll
                    for (int j = 0; j < 4; ++j)
                        acc[i][j] += pa[i][cc] * vv[cc][j];
        }
    }

#pragma unroll
    for (int i = 0; i < 4; ++i) {
        float4 o = make_float4(acc[i][0], acc[i][1], acc[i][2], acc[i][3]);
        *(float4*)&Ctx[(size_t)(b * SEQ + q0 + ty * 4 + i) * HID + h * HDIM + tx * 4] = o;
    }
}

// ---------------------------------------------------------------------------
extern "C" void kernel_launch(void* const* d_in, const int* in_sizes, int n_in,
                              void* d_out, int out_size) {
    const float* hs   = (const float*)d_in[0];
    const int*   mask = (const int*)d_in[1];
    const float* Wq   = (const float*)d_in[2];
    const float* bq   = (const float*)d_in[3];
    const float* Wk   = (const float*)d_in[4];
    const float* bk   = (const float*)d_in[5];
    const float* Wv   = (const float*)d_in[6];
    const float* bv   = (const float*)d_in[7];
    const float* Wo   = (const float*)d_in[8];
    const float* bo   = (const float*)d_in[9];

    float* out  = (float*)d_out;                       // [B,S,768]
    float* attn = out + (size_t)MROWS * HID;           // [B,12,S,S]

    float *Qp, *Kp, *Vp, *Cp, *Lp;
    cudaGetSymbolAddress((void**)&Qp, g_Q);
    cudaGetSymbolAddress((void**)&Kp, g_K);
    cudaGetSymbolAddress((void**)&Vp, g_V);
    cudaGetSymbolAddress((void**)&Cp, g_C);
    cudaGetSymbolAddress((void**)&Lp, g_L);

    dim3 gg(HID / 64, MROWS / 128);   // (12, 64)
    gemm_xwT<<<gg, 256>>>(hs, Wq, bq, Qp);
    gemm_xwT<<<gg, 256>>>(hs, Wk, bk, Kp);
    gemm_xwT<<<gg, 256>>>(hs, Wv, bv, Vp);

    dim3 ga(SEQ / 64, BATCH * NHEAD); // (64, 24)
    attn_pass1<<<ga, 256>>>(Qp, Kp, mask, attn, Lp);
    attn_pass2<<<ga, 256>>>(Vp, Lp, attn, Cp);

    gemm_xwT<<<gg, 256>>>(Cp, Wo, bo, out);
}

// round 6
// speedup vs baseline: 2.2147x; 2.2147x over previous
#include <cuda_runtime.h>
#include <math.h>

#define BATCH 2
#define SEQ   4096
#define HID   768
#define NHEAD 12
#define HDIM  64
#define MROWS (BATCH * SEQ)   // 8192

// ---------------- scratch (device globals: allocation-free) ----------------
__device__ float g_Q[(size_t)MROWS * HID];
__device__ float g_K[(size_t)MROWS * HID];
__device__ float g_V[(size_t)MROWS * HID];
__device__ float g_C[(size_t)MROWS * HID];
__device__ float g_L[(size_t)BATCH * NHEAD * SEQ];

// ---------------- tf32 helpers ----------------
__device__ __forceinline__ unsigned f2tf(float x) {
    unsigned u;
    asm("cvt.rna.tf32.f32 %0, %1;" : "=r"(u) : "f"(x));
    return u;
}

__device__ __forceinline__ void mma_tf32(float* c, unsigned a0, unsigned a1,
                                         unsigned a2, unsigned a3,
                                         unsigned b0, unsigned b1) {
    asm volatile(
        "mma.sync.aligned.m16n8k8.row.col.f32.tf32.tf32.f32 "
        "{%0,%1,%2,%3}, {%4,%5,%6,%7}, {%8,%9}, {%0,%1,%2,%3};\n"
        : "+f"(c[0]), "+f"(c[1]), "+f"(c[2]), "+f"(c[3])
        : "r"(a0), "r"(a1), "r"(a2), "r"(a3), "r"(b0), "r"(b1));
}

// ---------------------------------------------------------------------------
// GEMM: Y[M,768] = X[M,768] @ W[768,768]^T + bias  (tf32 mma)
// CTA 128x128, 8 warps (4 m x 2 n), warp = 32x64, k-chunk 32.
// ---------------------------------------------------------------------------
#define GP 36
__global__ __launch_bounds__(256) void gemm_tf32(
    const float* __restrict__ X, const float* __restrict__ W,
    const float* __restrict__ bias, float* __restrict__ Y) {
    __shared__ unsigned Xs[128 * GP];
    __shared__ unsigned Ws[128 * GP];

    int tid = threadIdx.x, lane = tid & 31, wid = tid >> 5;
    int wm = wid & 3, wn = wid >> 2;
    int row0 = blockIdx.y * 128, col0 = blockIdx.x * 128;

    float acc[2][8][4];
#pragma unroll
    for (int mt = 0; mt < 2; mt++)
#pragma unroll
        for (int nt = 0; nt < 8; nt++)
#pragma unroll
            for (int j = 0; j < 4; j++) acc[mt][nt][j] = 0.f;

    int lr = tid >> 1, lc = (tid & 1) * 16;
    const float* xg = X + (size_t)(row0 + lr) * HID + lc;
    const float* wg = W + (size_t)(col0 + lr) * HID + lc;

    for (int k0 = 0; k0 < HID; k0 += 32) {
#pragma unroll
        for (int i = 0; i < 16; i += 4) {
            float4 v = *(const float4*)(xg + k0 + i);
            uint4 u = make_uint4(f2tf(v.x), f2tf(v.y), f2tf(v.z), f2tf(v.w));
            *(uint4*)&Xs[lr * GP + lc + i] = u;
            float4 w = *(const float4*)(wg + k0 + i);
            uint4 uw = make_uint4(f2tf(w.x), f2tf(w.y), f2tf(w.z), f2tf(w.w));
            *(uint4*)&Ws[lr * GP + lc + i] = uw;
        }
        __syncthreads();
#pragma unroll
        for (int kk = 0; kk < 4; kk++) {
            unsigned a[2][4];
#pragma unroll
            for (int mt = 0; mt < 2; mt++) {
                int r = wm * 32 + mt * 16 + (lane >> 2);
                int c = kk * 8 + (lane & 3);
                a[mt][0] = Xs[r * GP + c];
                a[mt][1] = Xs[(r + 8) * GP + c];
                a[mt][2] = Xs[r * GP + c + 4];
                a[mt][3] = Xs[(r + 8) * GP + c + 4];
            }
#pragma unroll
            for (int nt = 0; nt < 8; nt++) {
                int n = wn * 64 + nt * 8 + (lane >> 2);
                int c = kk * 8 + (lane & 3);
                unsigned b0 = Ws[n * GP + c], b1 = Ws[n * GP + c + 4];
                mma_tf32(acc[0][nt], a[0][0], a[0][1], a[0][2], a[0][3], b0, b1);
                mma_tf32(acc[1][nt], a[1][0], a[1][1], a[1][2], a[1][3], b0, b1);
            }
        }
        __syncthreads();
    }

#pragma unroll
    for (int mt = 0; mt < 2; mt++)
#pragma unroll
        for (int nt = 0; nt < 8; nt++) {
            int r = row0 + wm * 32 + mt * 16 + (lane >> 2);
            int c = col0 + wn * 64 + nt * 8 + 2 * (lane & 3);
            float bx = bias[c], by = bias[c + 1];
            float2 o0 = make_float2(acc[mt][nt][0] + bx, acc[mt][nt][1] + by);
            float2 o1 = make_float2(acc[mt][nt][2] + bx, acc[mt][nt][3] + by);
            *(float2*)&Y[(size_t)r * HID + c] = o0;
            *(float2*)&Y[(size_t)(r + 8) * HID + c] = o1;
        }
}

// ---------------------------------------------------------------------------
// Pass 1: row sums L only (no attn write). CTA: 128 q-rows, 8 warps x 16 rows.
// ---------------------------------------------------------------------------
#define AP 68
__global__ __launch_bounds__(256) void attn_lsum(
    const float* __restrict__ Q, const float* __restrict__ K,
    const int* __restrict__ mask, float* __restrict__ L) {
    extern __shared__ unsigned sm1[];
    unsigned* Qs = sm1;                    // 128*AP
    unsigned* Ks = sm1 + 128 * AP;         // 64*AP
    int* msk = (int*)(sm1 + 192 * AP);     // 64

    int tid = threadIdx.x, lane = tid & 31, wid = tid >> 5;
    int bh = blockIdx.y, b = bh / NHEAD, h = bh - b * NHEAD;
    int q0 = blockIdx.x * 128;

    {
        int r = tid >> 1, c0 = (tid & 1) * 32;
        const float* qg = Q + (size_t)(b * SEQ + q0 + r) * HID + h * HDIM + c0;
#pragma unroll
        for (int i = 0; i < 32; i += 4) {
            float4 v = *(const float4*)(qg + i);
            *(uint4*)&Qs[r * AP + c0 + i] =
                make_uint4(f2tf(v.x), f2tf(v.y), f2tf(v.z), f2tf(v.w));
        }
    }

    float sA = 0.f, sB = 0.f;
    const int* mg = mask + b * SEQ;
    const float* kgb = K + (size_t)(b * SEQ) * HID + h * HDIM;

    for (int kt = 0; kt < SEQ / 64; ++kt) {
        __syncthreads();
        {
            int r = tid >> 2, c0 = (tid & 3) * 16;
            const float* kg = kgb + (size_t)(kt * 64 + r) * HID + c0;
#pragma unroll
            for (int i = 0; i < 16; i += 4) {
                float4 v = *(const float4*)(kg + i);
                *(uint4*)&Ks[r * AP + c0 + i] =
                    make_uint4(f2tf(v.x), f2tf(v.y), f2tf(v.z), f2tf(v.w));
            }
            if (tid < 64) msk[tid] = mg[kt * 64 + tid];
        }
        __syncthreads();

        float acc[8][4];
#pragma unroll
        for (int nt = 0; nt < 8; nt++)
#pragma unroll
            for (int j = 0; j < 4; j++) acc[nt][j] = 0.f;

#pragma unroll
        for (int kk = 0; kk < 8; kk++) {
            int r = wid * 16 + (lane >> 2), c = kk * 8 + (lane & 3);
            unsigned a0 = Qs[r * AP + c], a1 = Qs[(r + 8) * AP + c];
            unsigned a2 = Qs[r * AP + c + 4], a3 = Qs[(r + 8) * AP + c + 4];
#pragma unroll
            for (int nt = 0; nt < 8; nt++) {
                int n = nt * 8 + (lane >> 2);
                unsigned b0 = Ks[n * AP + c], b1 = Ks[n * AP + c + 4];
                mma_tf32(acc[nt], a0, a1, a2, a3, b0, b1);
            }
        }

#pragma unroll
        for (int nt = 0; nt < 8; nt++) {
            int c = nt * 8 + 2 * (lane & 3);
            float m0 = msk[c] ? 1.f : 0.f, m1 = msk[c + 1] ? 1.f : 0.f;
            sA += m0 * __expf(acc[nt][0] * 0.125f) + m1 * __expf(acc[nt][1] * 0.125f);
            sB += m0 * __expf(acc[nt][2] * 0.125f) + m1 * __expf(acc[nt][3] * 0.125f);
        }
    }

    sA += __shfl_xor_sync(0xffffffffu, sA, 1);
    sA += __shfl_xor_sync(0xffffffffu, sA, 2);
    sB += __shfl_xor_sync(0xffffffffu, sB, 1);
    sB += __shfl_xor_sync(0xffffffffu, sB, 2);
    if ((lane & 3) == 0) {
        int r = q0 + wid * 16 + (lane >> 2);
        L[(size_t)bh * SEQ + r] = sA;
        L[(size_t)bh * SEQ + r + 8] = sB;
    }
}

// ---------------------------------------------------------------------------
// Pass 2: recompute scores, normalize, write attn weights (once), fuse P@V.
// ---------------------------------------------------------------------------
__global__ __launch_bounds__(256) void attn_pass2(
    const float* __restrict__ Q, const float* __restrict__ K,
    const float* __restrict__ V, const int* __restrict__ mask,
    const float* __restrict__ L, float* __restrict__ attn,
    float* __restrict__ Ctx) {
    extern __shared__ unsigned sm2[];
    unsigned* Qs = sm2;                    // 128*AP
    unsigned* Ks = sm2 + 128 * AP;         // 64*AP
    unsigned* Vs = sm2 + 192 * AP;         // 64*AP
    unsigned* Ps = sm2 + 256 * AP;         // 128*AP (16*AP per warp)
    int* msk = (int*)(sm2 + 384 * AP);     // 64

    int tid = threadIdx.x, lane = tid & 31, wid = tid >> 5;
    int bh = blockIdx.y, b = bh / NHEAD, h = bh - b * NHEAD;
    int q0 = blockIdx.x * 128;

    {
        int r = tid >> 1, c0 = (tid & 1) * 32;
        const float* qg = Q + (size_t)(b * SEQ + q0 + r) * HID + h * HDIM + c0;
#pragma unroll
        for (int i = 0; i < 32; i += 4) {
            float4 v = *(const float4*)(qg + i);
            *(uint4*)&Qs[r * AP + c0 + i] =
                make_uint4(f2tf(v.x), f2tf(v.y), f2tf(v.z), f2tf(v.w));
        }
    }

    int rA = q0 + wid * 16 + (lane >> 2);
    float liA = 1.0f / L[(size_t)bh * SEQ + rA];
    float liB = 1.0f / L[(size_t)bh * SEQ + rA + 8];

    float ctx[8][4];
#pragma unroll
    for (int nt = 0; nt < 8; nt++)
#pragma unroll
        for (int j = 0; j < 4; j++) ctx[nt][j] = 0.f;

    const int* mg = mask + b * SEQ;
    const float* kgb = K + (size_t)(b * SEQ) * HID + h * HDIM;
    const float* vgb = V + (size_t)(b * SEQ) * HID + h * HDIM;
    unsigned* Pw = Ps + wid * 16 * AP;
    float* abase = attn + ((size_t)bh * SEQ + q0 + wid * 16) * SEQ;

    for (int kt = 0; kt < SEQ / 64; ++kt) {
        __syncthreads();
        {
            int r = tid >> 2, c0 = (tid & 3) * 16;
            const float* kg = kgb + (size_t)(kt * 64 + r) * HID + c0;
            const float* vg = vgb + (size_t)(kt * 64 + r) * HID + c0;
#pragma unroll
            for (int i = 0; i < 16; i += 4) {
                float4 v = *(const float4*)(kg + i);
                *(uint4*)&Ks[r * AP + c0 + i] =
                    make_uint4(f2tf(v.x), f2tf(v.y), f2tf(v.z), f2tf(v.w));
                float4 w = *(const float4*)(vg + i);
                *(uint4*)&Vs[r * AP + c0 + i] =
                    make_uint4(f2tf(w.x), f2tf(w.y), f2tf(w.z), f2tf(w.w));
            }
            if (tid < 64) msk[tid] = mg[kt * 64 + tid];
        }
        __syncthreads();

        float acc[8][4];
#pragma unroll
        for (int nt = 0; nt < 8; nt++)
#pragma unroll
            for (int j = 0; j < 4; j++) acc[nt][j] = 0.f;

#pragma unroll
        for (int kk = 0; kk < 8; kk++) {
            int r = wid * 16 + (lane >> 2), c = kk * 8 + (lane & 3);
            unsigned a0 = Qs[r * AP + c], a1 = Qs[(r + 8) * AP + c];
            unsigned a2 = Qs[r * AP + c + 4], a3 = Qs[(r + 8) * AP + c + 4];
#pragma unroll
            for (int nt = 0; nt < 8; nt++) {
                int n = nt * 8 + (lane >> 2);
                unsigned b0 = Ks[n * AP + c], b1 = Ks[n * AP + c + 4];
                mma_tf32(acc[nt], a0, a1, a2, a3, b0, b1);
            }
        }

        // normalize, write attn (fp32), stage tf32 P for the V mma
        int rr = lane >> 2;
#pragma unroll
        for (int nt = 0; nt < 8; nt++) {
            int c = nt * 8 + 2 * (lane & 3);
            float m0 = msk[c] ? 1.f : 0.f, m1 = msk[c + 1] ? 1.f : 0.f;
            float w0 = m0 * __expf(acc[nt][0] * 0.125f) * liA;
            float w1 = m1 * __expf(acc[nt][1] * 0.125f) * liA;
            float w2 = m0 * __expf(acc[nt][2] * 0.125f) * liB;
            float w3 = m1 * __expf(acc[nt][3] * 0.125f) * liB;
            *(float2*)&abase[(size_t)rr * SEQ + kt * 64 + c] = make_float2(w0, w1);
            *(float2*)&abase[(size_t)(rr + 8) * SEQ + kt * 64 + c] = make_float2(w2, w3);
            Pw[rr * AP + c] = f2tf(w0);
            Pw[rr * AP + c + 1] = f2tf(w1);
            Pw[(rr + 8) * AP + c] = f2tf(w2);
            Pw[(rr + 8) * AP + c + 1] = f2tf(w3);
        }
        __syncwarp();

        // ctx += P @ V
#pragma unroll
        for (int kk = 0; kk < 8; kk++) {
            int c = kk * 8 + (lane & 3);
            unsigned a0 = Pw[rr * AP + c], a1 = Pw[(rr + 8) * AP + c];
            unsigned a2 = Pw[rr * AP + c + 4], a3 = Pw[(rr + 8) * AP + c + 4];
#pragma unroll
            for (int nt = 0; nt < 8; nt++) {
                unsigned b0 = Vs[(kk * 8 + (lane & 3)) * AP + nt * 8 + (lane >> 2)];
                unsigned b1 = Vs[(kk * 8 + (lane & 3) + 4) * AP + nt * 8 + (lane >> 2)];
                mma_tf32(ctx[nt], a0, a1, a2, a3, b0, b1);
            }
        }
        __syncwarp();
    }

#pragma unroll
    for (int nt = 0; nt < 8; nt++) {
        int rr = lane >> 2;
        int c = nt * 8 + 2 * (lane & 3);
        size_t base = (size_t)(b * SEQ + q0 + wid * 16 + rr) * HID + h * HDIM + c;
        *(float2*)&Ctx[base] = make_float2(ctx[nt][0], ctx[nt][1]);
        *(float2*)&Ctx[base + (size_t)8 * HID] = make_float2(ctx[nt][2], ctx[nt][3]);
    }
}

// ---------------------------------------------------------------------------
extern "C" void kernel_launch(void* const* d_in, const int* in_sizes, int n_in,
                              void* d_out, int out_size) {
    const float* hs   = (const float*)d_in[0];
    const int*   mask = (const int*)d_in[1];
    const float* Wq   = (const float*)d_in[2];
    const float* bq   = (const float*)d_in[3];
    const float* Wk   = (const float*)d_in[4];
    const float* bk   = (const float*)d_in[5];
    const float* Wv   = (const float*)d_in[6];
    const float* bv   = (const float*)d_in[7];
    const float* Wo   = (const float*)d_in[8];
    const float* bo   = (const float*)d_in[9];

    float* out  = (float*)d_out;                       // [B,S,768]
    float* attn = out + (size_t)MROWS * HID;           // [B,12,S,S]

    float *Qp, *Kp, *Vp, *Cp, *Lp;
    cudaGetSymbolAddress((void**)&Qp, g_Q);
    cudaGetSymbolAddress((void**)&Kp, g_K);
    cudaGetSymbolAddress((void**)&Vp, g_V);
    cudaGetSymbolAddress((void**)&Cp, g_C);
    cudaGetSymbolAddress((void**)&Lp, g_L);

    static int smem_set = 0;
    int smem1 = (192 * AP) * 4 + 64 * 4;               // ~52.5 KB
    int smem2 = (384 * AP) * 4 + 64 * 4;               // ~104.7 KB
    if (!smem_set) {
        cudaFuncSetAttribute(attn_lsum,
            cudaFuncAttributeMaxDynamicSharedMemorySize, smem1);
        cudaFuncSetAttribute(attn_pass2,
            cudaFuncAttributeMaxDynamicSharedMemorySize, smem2);
        smem_set = 1;
    }

    dim3 gg(HID / 128, MROWS / 128);   // (6, 64)
    gemm_tf32<<<gg, 256>>>(hs, Wq, bq, Qp);
    gemm_tf32<<<gg, 256>>>(hs, Wk, bk, Kp);
    gemm_tf32<<<gg, 256>>>(hs, Wv, bv, Vp);

    dim3 ga(SEQ / 128, BATCH * NHEAD); // (32, 24)
    attn_lsum<<<ga, 256, smem1>>>(Qp, Kp, mask, Lp);
    attn_pass2<<<ga, 256, smem2>>>(Qp, Kp, Vp, mask, Lp, attn, Cp);

    gemm_tf32<<<gg, 256>>>(Cp, Wo, bo, out);
}

// round 7
// speedup vs baseline: 2.2152x; 1.0002x over previous
#include <cuda_runtime.h>
#include <math.h>

#define BATCH 2
#define SEQ   4096
#define HID   768
#define NHEAD 12
#define HDIM  64
#define MROWS (BATCH * SEQ)   // 8192

// ---------------- scratch (device globals: allocation-free) ----------------
__device__ float g_Q[(size_t)MROWS * HID];
__device__ float g_K[(size_t)MROWS * HID];
__device__ float g_V[(size_t)MROWS * HID];
__device__ float g_C[(size_t)MROWS * HID];
__device__ float g_L[(size_t)BATCH * NHEAD * SEQ];

// ---------------- tf32 helpers ----------------
__device__ __forceinline__ unsigned f2tf(float x) {
    unsigned u;
    asm("cvt.rna.tf32.f32 %0, %1;" : "=r"(u) : "f"(x));
    return u;
}

__device__ __forceinline__ void mma_tf32(float* c, unsigned a0, unsigned a1,
                                         unsigned a2, unsigned a3,
                                         unsigned b0, unsigned b1) {
    asm volatile(
        "mma.sync.aligned.m16n8k8.row.col.f32.tf32.tf32.f32 "
        "{%0,%1,%2,%3}, {%4,%5,%6,%7}, {%8,%9}, {%0,%1,%2,%3};\n"
        : "+f"(c[0]), "+f"(c[1]), "+f"(c[2]), "+f"(c[3])
        : "r"(a0), "r"(a1), "r"(a2), "r"(a3), "r"(b0), "r"(b1));
}

// ---------------------------------------------------------------------------
// GEMM: Y[M,768] = X[M,768] @ W[768,768]^T + bias  (tf32 mma)
// CTA 128x128, 8 warps (4 m x 2 n), warp = 32x64, k-chunk 32.
// ---------------------------------------------------------------------------
#define GP 36
__global__ __launch_bounds__(256) void gemm_tf32(
    const float* __restrict__ X, const float* __restrict__ W,
    const float* __restrict__ bias, float* __restrict__ Y) {
    __shared__ unsigned Xs[128 * GP];
    __shared__ unsigned Ws[128 * GP];

    int tid = threadIdx.x, lane = tid & 31, wid = tid >> 5;
    int wm = wid & 3, wn = wid >> 2;
    int row0 = blockIdx.y * 128, col0 = blockIdx.x * 128;

    float acc[2][8][4];
#pragma unroll
    for (int mt = 0; mt < 2; mt++)
#pragma unroll
        for (int nt = 0; nt < 8; nt++)
#pragma unroll
            for (int j = 0; j < 4; j++) acc[mt][nt][j] = 0.f;

    int lr = tid >> 1, lc = (tid & 1) * 16;
    const float* xg = X + (size_t)(row0 + lr) * HID + lc;
    const float* wg = W + (size_t)(col0 + lr) * HID + lc;

    for (int k0 = 0; k0 < HID; k0 += 32) {
#pragma unroll
        for (int i = 0; i < 16; i += 4) {
            float4 v = *(const float4*)(xg + k0 + i);
            uint4 u = make_uint4(f2tf(v.x), f2tf(v.y), f2tf(v.z), f2tf(v.w));
            *(uint4*)&Xs[lr * GP + lc + i] = u;
            float4 w = *(const float4*)(wg + k0 + i);
            uint4 uw = make_uint4(f2tf(w.x), f2tf(w.y), f2tf(w.z), f2tf(w.w));
            *(uint4*)&Ws[lr * GP + lc + i] = uw;
        }
        __syncthreads();
#pragma unroll
        for (int kk = 0; kk < 4; kk++) {
            unsigned a[2][4];
#pragma unroll
            for (int mt = 0; mt < 2; mt++) {
                int r = wm * 32 + mt * 16 + (lane >> 2);
                int c = kk * 8 + (lane & 3);
                a[mt][0] = Xs[r * GP + c];
                a[mt][1] = Xs[(r + 8) * GP + c];
                a[mt][2] = Xs[r * GP + c + 4];
                a[mt][3] = Xs[(r + 8) * GP + c + 4];
            }
#pragma unroll
            for (int nt = 0; nt < 8; nt++) {
                int n = wn * 64 + nt * 8 + (lane >> 2);
                int c = kk * 8 + (lane & 3);
                unsigned b0 = Ws[n * GP + c], b1 = Ws[n * GP + c + 4];
                mma_tf32(acc[0][nt], a[0][0], a[0][1], a[0][2], a[0][3], b0, b1);
                mma_tf32(acc[1][nt], a[1][0], a[1][1], a[1][2], a[1][3], b0, b1);
            }
        }
        __syncthreads();
    }

#pragma unroll
    for (int mt = 0; mt < 2; mt++)
#pragma unroll
        for (int nt = 0; nt < 8; nt++) {
            int r = row0 + wm * 32 + mt * 16 + (lane >> 2);
            int c = col0 + wn * 64 + nt * 8 + 2 * (lane & 3);
            float bx = bias[c], by = bias[c + 1];
            float2 o0 = make_float2(acc[mt][nt][0] + bx, acc[mt][nt][1] + by);
            float2 o1 = make_float2(acc[mt][nt][2] + bx, acc[mt][nt][3] + by);
            *(float2*)&Y[(size_t)r * HID + c] = o0;
            *(float2*)&Y[(size_t)(r + 8) * HID + c] = o1;
        }
}

// ---------------------------------------------------------------------------
// Pass 1: row sums L only (no attn write). CTA: 128 q-rows, 8 warps x 16 rows.
// ---------------------------------------------------------------------------
#define AP 68
__global__ __launch_bounds__(256) void attn_lsum(
    const float* __restrict__ Q, const float* __restrict__ K,
    const int* __restrict__ mask, float* __restrict__ L) {
    extern __shared__ unsigned sm1[];
    unsigned* Qs = sm1;                    // 128*AP
    unsigned* Ks = sm1 + 128 * AP;         // 64*AP
    int* msk = (int*)(sm1 + 192 * AP);     // 64

    int tid = threadIdx.x, lane = tid & 31, wid = tid >> 5;
    int bh = blockIdx.y, b = bh / NHEAD, h = bh - b * NHEAD;
    int q0 = blockIdx.x * 128;

    {
        int r = tid >> 1, c0 = (tid & 1) * 32;
        const float* qg = Q + (size_t)(b * SEQ + q0 + r) * HID + h * HDIM + c0;
#pragma unroll
        for (int i = 0; i < 32; i += 4) {
            float4 v = *(const float4*)(qg + i);
            *(uint4*)&Qs[r * AP + c0 + i] =
                make_uint4(f2tf(v.x), f2tf(v.y), f2tf(v.z), f2tf(v.w));
        }
    }

    float sA = 0.f, sB = 0.f;
    const int* mg = mask + b * SEQ;
    const float* kgb = K + (size_t)(b * SEQ) * HID + h * HDIM;

    for (int kt = 0; kt < SEQ / 64; ++kt) {
        __syncthreads();
        {
            int r = tid >> 2, c0 = (tid & 3) * 16;
            const float* kg = kgb + (size_t)(kt * 64 + r) * HID + c0;
#pragma unroll
            for (int i = 0; i < 16; i += 4) {
                float4 v = *(const float4*)(kg + i);
                *(uint4*)&Ks[r * AP + c0 + i] =
                    make_uint4(f2tf(v.x), f2tf(v.y), f2tf(v.z), f2tf(v.w));
            }
            if (tid < 64) msk[tid] = mg[kt * 64 + tid];
        }
        __syncthreads();

        float acc[8][4];
#pragma unroll
        for (int nt = 0; nt < 8; nt++)
#pragma unroll
            for (int j = 0; j < 4; j++) acc[nt][j] = 0.f;

#pragma unroll
        for (int kk = 0; kk < 8; kk++) {
            int r = wid * 16 + (lane >> 2), c = kk * 8 + (lane & 3);
            unsigned a0 = Qs[r * AP + c], a1 = Qs[(r + 8) * AP + c];
            unsigned a2 = Qs[r * AP + c + 4], a3 = Qs[(r + 8) * AP + c + 4];
#pragma unroll
            for (int nt = 0; nt < 8; nt++) {
                int n = nt * 8 + (lane >> 2);
                unsigned b0 = Ks[n * AP + c], b1 = Ks[n * AP + c + 4];
                mma_tf32(acc[nt], a0, a1, a2, a3, b0, b1);
            }
        }

#pragma unroll
        for (int nt = 0; nt < 8; nt++) {
            int c = nt * 8 + 2 * (lane & 3);
            float m0 = msk[c] ? 1.f : 0.f, m1 = msk[c + 1] ? 1.f : 0.f;
            sA += m0 * __expf(acc[nt][0] * 0.125f) + m1 * __expf(acc[nt][1] * 0.125f);
            sB += m0 * __expf(acc[nt][2] * 0.125f) + m1 * __expf(acc[nt][3] * 0.125f);
        }
    }

    sA += __shfl_xor_sync(0xffffffffu, sA, 1);
    sA += __shfl_xor_sync(0xffffffffu, sA, 2);
    sB += __shfl_xor_sync(0xffffffffu, sB, 1);
    sB += __shfl_xor_sync(0xffffffffu, sB, 2);
    if ((lane & 3) == 0) {
        int r = q0 + wid * 16 + (lane >> 2);
        L[(size_t)bh * SEQ + r] = sA;
        L[(size_t)bh * SEQ + r + 8] = sB;
    }
}

// ---------------------------------------------------------------------------
// Pass 2: recompute scores, normalize, write attn weights (once), fuse P@V.
// ---------------------------------------------------------------------------
__global__ __launch_bounds__(256) void attn_pass2(
    const float* __restrict__ Q, const float* __restrict__ K,
    const float* __restrict__ V, const int* __restrict__ mask,
    const float* __restrict__ L, float* __restrict__ attn,
    float* __restrict__ Ctx) {
    extern __shared__ unsigned sm2[];
    unsigned* Qs = sm2;                    // 128*AP
    unsigned* Ks = sm2 + 128 * AP;         // 64*AP
    unsigned* Vs = sm2 + 192 * AP;         // 64*AP
    unsigned* Ps = sm2 + 256 * AP;         // 128*AP (16*AP per warp)
    int* msk = (int*)(sm2 + 384 * AP);     // 64

    int tid = threadIdx.x, lane = tid & 31, wid = tid >> 5;
    int bh = blockIdx.y, b = bh / NHEAD, h = bh - b * NHEAD;
    int q0 = blockIdx.x * 128;

    {
        int r = tid >> 1, c0 = (tid & 1) * 32;
        const float* qg = Q + (size_t)(b * SEQ + q0 + r) * HID + h * HDIM + c0;
#pragma unroll
        for (int i = 0; i < 32; i += 4) {
            float4 v = *(const float4*)(qg + i);
            *(uint4*)&Qs[r * AP + c0 + i] =
                make_uint4(f2tf(v.x), f2tf(v.y), f2tf(v.z), f2tf(v.w));
        }
    }

    int rA = q0 + wid * 16 + (lane >> 2);
    float liA = 1.0f / L[(size_t)bh * SEQ + rA];
    float liB = 1.0f / L[(size_t)bh * SEQ + rA + 8];

    float ctx[8][4];
#pragma unroll
    for (int nt = 0; nt < 8; nt++)
#pragma unroll
        for (int j = 0; j < 4; j++) ctx[nt][j] = 0.f;

    const int* mg = mask + b * SEQ;
    const float* kgb = K + (size_t)(b * SEQ) * HID + h * HDIM;
    const float* vgb = V + (size_t)(b * SEQ) * HID + h * HDIM;
    unsigned* Pw = Ps + wid * 16 * AP;
    float* abase = attn + ((size_t)bh * SEQ + q0 + wid * 16) * SEQ;

    for (int kt = 0; kt < SEQ / 64; ++kt) {
        __syncthreads();
        {
            int r = tid >> 2, c0 = (tid & 3) * 16;
            const float* kg = kgb + (size_t)(kt * 64 + r) * HID + c0;
            const float* vg = vgb + (size_t)(kt * 64 + r) * HID + c0;
#pragma unroll
            for (int i = 0; i < 16; i += 4) {
                float4 v = *(const float4*)(kg + i);
                *(uint4*)&Ks[r * AP + c0 + i] =
                    make_uint4(f2tf(v.x), f2tf(v.y), f2tf(v.z), f2tf(v.w));
                float4 w = *(const float4*)(vg + i);
                *(uint4*)&Vs[r * AP + c0 + i] =
                    make_uint4(f2tf(w.x), f2tf(w.y), f2tf(w.z), f2tf(w.w));
            }
            if (tid < 64) msk[tid] = mg[kt * 64 + tid];
        }
        __syncthreads();

        float acc[8][4];
#pragma unroll
        for (int nt = 0; nt < 8; nt++)
#pragma unroll
            for (int j = 0; j < 4; j++) acc[nt][j] = 0.f;

#pragma unroll
        for (int kk = 0; kk < 8; kk++) {
            int r = wid * 16 + (lane >> 2), c = kk * 8 + (lane & 3);
            unsigned a0 = Qs[r * AP + c], a1 = Qs[(r + 8) * AP + c];
            unsigned a2 = Qs[r * AP + c + 4], a3 = Qs[(r + 8) * AP + c + 4];
#pragma unroll
            for (int nt = 0; nt < 8; nt++) {
                int n = nt * 8 + (lane >> 2);
                unsigned b0 = Ks[n * AP + c], b1 = Ks[n * AP + c + 4];
                mma_tf32(acc[nt], a0, a1, a2, a3, b0, b1);
            }
        }

        // normalize, write attn (fp32), stage tf32 P for the V mma
        int rr = lane >> 2;
#pragma unroll
        for (int nt = 0; nt < 8; nt++) {
            int c = nt * 8 + 2 * (lane & 3);
            float m0 = msk[c] ? 1.f : 0.f, m1 = msk[c + 1] ? 1.f : 0.f;
            float w0 = m0 * __expf(acc[nt][0] * 0.125f) * liA;
            float w1 = m1 * __expf(acc[nt][1] * 0.125f) * liA;
            float w2 = m0 * __expf(acc[nt][2] * 0.125f) * liB;
            float w3 = m1 * __expf(acc[nt][3] * 0.125f) * liB;
            *(float2*)&abase[(size_t)rr * SEQ + kt * 64 + c] = make_float2(w0, w1);
            *(float2*)&abase[(size_t)(rr + 8) * SEQ + kt * 64 + c] = make_float2(w2, w3);
            Pw[rr * AP + c] = f2tf(w0);
            Pw[rr * AP + c + 1] = f2tf(w1);
            Pw[(rr + 8) * AP + c] = f2tf(w2);
            Pw[(rr + 8) * AP + c + 1] = f2tf(w3);
        }
        __syncwarp();

        // ctx += P @ V
#pragma unroll
        for (int kk = 0; kk < 8; kk++) {
            int c = kk * 8 + (lane & 3);
            unsigned a0 = Pw[rr * AP + c], a1 = Pw[(rr + 8) * AP + c];
            unsigned a2 = Pw[rr * AP + c + 4], a3 = Pw[(rr + 8) * AP + c + 4];
#pragma unroll
            for (int nt = 0; nt < 8; nt++) {
                unsigned b0 = Vs[(kk * 8 + (lane & 3)) * AP + nt * 8 + (lane >> 2)];
                unsigned b1 = Vs[(kk * 8 + (lane & 3) + 4) * AP + nt * 8 + (lane >> 2)];
                mma_tf32(ctx[nt], a0, a1, a2, a3, b0, b1);
            }
        }
        __syncwarp();
    }

#pragma unroll
    for (int nt = 0; nt < 8; nt++) {
        int rr = lane >> 2;
        int c = nt * 8 + 2 * (lane & 3);
        size_t base = (size_t)(b * SEQ + q0 + wid * 16 + rr) * HID + h * HDIM + c;
        *(float2*)&Ctx[base] = make_float2(ctx[nt][0], ctx[nt][1]);
        *(float2*)&Ctx[base + (size_t)8 * HID] = make_float2(ctx[nt][2], ctx[nt][3]);
    }
}

// ---------------------------------------------------------------------------
extern "C" void kernel_launch(void* const* d_in, const int* in_sizes, int n_in,
                              void* d_out, int out_size) {
    const float* hs   = (const float*)d_in[0];
    const int*   mask = (const int*)d_in[1];
    const float* Wq   = (const float*)d_in[2];
    const float* bq   = (const float*)d_in[3];
    const float* Wk   = (const float*)d_in[4];
    const float* bk   = (const float*)d_in[5];
    const float* Wv   = (const float*)d_in[6];
    const float* bv   = (const float*)d_in[7];
    const float* Wo   = (const float*)d_in[8];
    const float* bo   = (const float*)d_in[9];

    float* out  = (float*)d_out;                       // [B,S,768]
    float* attn = out + (size_t)MROWS * HID;           // [B,12,S,S]

    float *Qp, *Kp, *Vp, *Cp, *Lp;
    cudaGetSymbolAddress((void**)&Qp, g_Q);
    cudaGetSymbolAddress((void**)&Kp, g_K);
    cudaGetSymbolAddress((void**)&Vp, g_V);
    cudaGetSymbolAddress((void**)&Cp, g_C);
    cudaGetSymbolAddress((void**)&Lp, g_L);

    static int smem_set = 0;
    int smem1 = (192 * AP) * 4 + 64 * 4;               // ~52.5 KB
    int smem2 = (384 * AP) * 4 + 64 * 4;               // ~104.7 KB
    if (!smem_set) {
        cudaFuncSetAttribute(attn_lsum,
            cudaFuncAttributeMaxDynamicSharedMemorySize, smem1);
        cudaFuncSetAttribute(attn_pass2,
            cudaFuncAttributeMaxDynamicSharedMemorySize, smem2);
        smem_set = 1;
    }

    dim3 gg(HID / 128, MROWS / 128);   // (6, 64)
    gemm_tf32<<<gg, 256>>>(hs, Wq, bq, Qp);
    gemm_tf32<<<gg, 256>>>(hs, Wk, bk, Kp);
    gemm_tf32<<<gg, 256>>>(hs, Wv, bv, Vp);

    dim3 ga(SEQ / 128, BATCH * NHEAD); // (32, 24)
    attn_lsum<<<ga, 256, smem1>>>(Qp, Kp, mask, Lp);
    attn_pass2<<<ga, 256, smem2>>>(Qp, Kp, Vp, mask, Lp, attn, Cp);

    gemm_tf32<<<gg, 256>>>(Cp, Wo, bo, out);
}